// round 1
// baseline (speedup 1.0000x reference)
#include <cuda_runtime.h>
#include <math.h>

#define BB   4
#define SS   512
#define EE   512
#define HH   8
#define DHH  64
#define HIDD 128

// ---------------- scratch (device globals; no allocation allowed) ----------------
__device__ float g_q[BB * SS * EE];
__device__ float g_k[BB * SS * EE];
__device__ float g_v[BB * SS * EE];
__device__ float g_scores[(size_t)BB * HH * SS * SS];   // 33.5 MB, clamped scores
__device__ float g_mean[BB * SS * SS];                  // head-mean
__device__ float g_t0[BB * SS * SS];                    // pre-affine transform map
__device__ float g_rowstats[BB * SS * 4];               // per-row {Sm, Sm2, St, St2}
__device__ float g_consts[BB * 2];                      // per-batch {c, d}
__device__ float g_attnout[BB * SS * EE];

// ---------------- block reductions ----------------
__device__ __forceinline__ float bredMax256(float v, float* red) {
    int t = threadIdx.x;
    red[t] = v; __syncthreads();
    for (int s = 128; s > 0; s >>= 1) {
        if (t < s) red[t] = fmaxf(red[t], red[t + s]);
        __syncthreads();
    }
    float r = red[0]; __syncthreads();
    return r;
}
__device__ __forceinline__ float bredSum256(float v, float* red) {
    int t = threadIdx.x;
    red[t] = v; __syncthreads();
    for (int s = 128; s > 0; s >>= 1) {
        if (t < s) red[t] += red[t + s];
        __syncthreads();
    }
    float r = red[0]; __syncthreads();
    return r;
}

// ---------------- GEMM: C[m,n] = scale * (sum_k A[m,k]*W[n,k] + bias[n]) ----------------
// 64x64 tile, BK=16, 256 threads, 4x4 per thread. Smem stored k-major for float4 reads.
__global__ void gemm_nt64(const float* __restrict__ A, const float* __restrict__ W,
                          const float* __restrict__ bias, float* __restrict__ C,
                          int M, int N, int K, float scale) {
    __shared__ __align__(16) float As[16][68];
    __shared__ __align__(16) float Ws[16][68];
    const int tx = threadIdx.x & 15, ty = threadIdx.x >> 4;
    const int m0 = blockIdx.y << 6, n0 = blockIdx.x << 6;
    float acc[4][4] = {};
    for (int k0 = 0; k0 < K; k0 += 16) {
        #pragma unroll
        for (int i = threadIdx.x; i < 1024; i += 256) {
            int r = i >> 4, c = i & 15;
            As[c][r] = A[(m0 + r) * K + k0 + c];
            Ws[c][r] = W[(n0 + r) * K + k0 + c];
        }
        __syncthreads();
        #pragma unroll
        for (int kk = 0; kk < 16; kk++) {
            float4 a = *(const float4*)&As[kk][ty << 2];
            float4 w = *(const float4*)&Ws[kk][tx << 2];
            float av[4] = {a.x, a.y, a.z, a.w};
            float wv[4] = {w.x, w.y, w.z, w.w};
            #pragma unroll
            for (int i = 0; i < 4; i++)
                #pragma unroll
                for (int j = 0; j < 4; j++)
                    acc[i][j] = fmaf(av[i], wv[j], acc[i][j]);
        }
        __syncthreads();
    }
    #pragma unroll
    for (int i = 0; i < 4; i++) {
        int m = m0 + (ty << 2) + i;
        #pragma unroll
        for (int j = 0; j < 4; j++) {
            int n = n0 + (tx << 2) + j;
            C[m * N + n] = scale * (acc[i][j] + bias[n]);
        }
    }
}

// ---------------- scores[b,h,i,j] = clip(q_h[i,:] . k_h[j,:], -15, 15) ----------------
__global__ void scores_kernel(const float* __restrict__ q, const float* __restrict__ k,
                              float* __restrict__ scores) {
    __shared__ __align__(16) float Qs[64][68];
    __shared__ __align__(16) float Ks[64][68];
    const int bh = blockIdx.z;
    const int b = bh >> 3, h = bh & 7;
    const float* qb = q + (b * SS) * EE + h * DHH;
    const float* kb = k + (b * SS) * EE + h * DHH;
    const int i0 = blockIdx.y << 6, j0 = blockIdx.x << 6;
    for (int idx = threadIdx.x; idx < 4096; idx += 256) {
        int r = idx >> 6, c = idx & 63;
        Qs[c][r] = qb[(i0 + r) * EE + c];
        Ks[c][r] = kb[(j0 + r) * EE + c];
    }
    __syncthreads();
    const int tx = threadIdx.x & 15, ty = threadIdx.x >> 4;
    float acc[4][4] = {};
    #pragma unroll
    for (int d = 0; d < 64; d++) {
        float4 a = *(const float4*)&Qs[d][ty << 2];
        float4 w = *(const float4*)&Ks[d][tx << 2];
        float av[4] = {a.x, a.y, a.z, a.w};
        float wv[4] = {w.x, w.y, w.z, w.w};
        #pragma unroll
        for (int i = 0; i < 4; i++)
            #pragma unroll
            for (int j = 0; j < 4; j++)
                acc[i][j] = fmaf(av[i], wv[j], acc[i][j]);
    }
    float* out = scores + ((size_t)bh * SS + i0) * SS + j0;
    #pragma unroll
    for (int i = 0; i < 4; i++)
        #pragma unroll
        for (int j = 0; j < 4; j++)
            out[((ty << 2) + i) * SS + (tx << 2) + j] =
                fminf(fmaxf(acc[i][j], -15.f), 15.f);
}

// ---------------- head mean ----------------
__global__ void mean_kernel(const float* __restrict__ scores, float* __restrict__ meanb) {
    int idx = blockIdx.x * blockDim.x + threadIdx.x;  // over B*S*S
    int b = idx >> 18;          // / (S*S)
    int r = idx & (SS * SS - 1);
    const float* p = scores + ((size_t)b * HH) * SS * SS + r;
    float s = 0.f;
    #pragma unroll
    for (int h = 0; h < HH; h++) s += p[(size_t)h * SS * SS];
    meanb[idx] = s * (1.f / HH);
}

// ---------------- per-row autopoietic transform -> t0, row stats ----------------
__global__ void rowtrans_kernel(const float* __restrict__ meanb,
                                const float* __restrict__ w1, const float* __restrict__ b1,
                                const float* __restrict__ w2, const float* __restrict__ b2,
                                float* __restrict__ t0, float* __restrict__ rowstats) {
    __shared__ float sw1[HIDD], sb1[HIDD], sw2[HIDD];
    __shared__ float red[256];
    const int row = blockIdx.x;  // b*S + i
    const float* m = meanb + (size_t)row * SS;
    if (threadIdx.x < HIDD) {
        sw1[threadIdx.x] = w1[threadIdx.x];
        sb1[threadIdx.x] = b1[threadIdx.x];
        sw2[threadIdx.x] = w2[threadIdx.x];
    }
    __syncthreads();
    const float b2v = b2[0];

    float mv[2], sg[2], pv[2], hv[2];
    float lmax = -1e30f;
    #pragma unroll
    for (int e = 0; e < 2; e++) {
        int j = threadIdx.x * 2 + e;
        float mm = m[j];
        mv[e] = mm;
        float scaled = fminf(fmaxf(mm, -8.f), 8.f) * 0.05f;
        scaled = fminf(fmaxf(scaled, -10.f), 10.f);
        float autov = b2v;
        #pragma unroll 8
        for (int hh = 0; hh < HIDD; hh++) {
            float hidv = fmaf(scaled, sw1[hh], sb1[hh]);
            hidv = fminf(fmaxf(hidv, 0.f), 5.f);   // relu(clip(x,-5,5))
            autov = fmaf(hidv, sw2[hh], autov);
        }
        autov = fminf(fmaxf(autov, -5.f), 5.f);
        float tay = fminf(fmaxf(1.f + 2.5f * autov, 0.5f), 1.5f);
        sg[e] = 1.f / (1.f + expf(-tay));
        float xc = fminf(fmaxf(mm, -10.f), 10.f);
        pv[e] = xc;
        lmax = fmaxf(lmax, xc);
    }
    // softmax p over row
    float rmax = bredMax256(lmax, red);
    float lsum = 0.f;
    #pragma unroll
    for (int e = 0; e < 2; e++) { pv[e] = expf(pv[e] - rmax); lsum += pv[e]; }
    float rsum = bredSum256(lsum, red);
    float inv = 1.f / rsum;
    // entropy -> Fm softmax (stable)
    float hmax = -1e30f;
    #pragma unroll
    for (int e = 0; e < 2; e++) {
        float p = pv[e] * inv;
        hv[e] = 3.f * (-p * logf(p + 1e-6f));
        hmax = fmaxf(hmax, hv[e]);
    }
    float rhmax = bredMax256(hmax, red);
    lsum = 0.f;
    #pragma unroll
    for (int e = 0; e < 2; e++) { hv[e] = expf(hv[e] - rhmax); lsum += hv[e]; }
    float rhsum = bredSum256(lsum, red);
    float inv2 = 1.f / rhsum;
    // t0 + stats
    float sm = 0.f, sm2 = 0.f, st = 0.f, st2 = 0.f;
    #pragma unroll
    for (int e = 0; e < 2; e++) {
        float t = sg[e] * hv[e] * inv2;
        t0[(size_t)row * SS + threadIdx.x * 2 + e] = t;
        sm += mv[e]; sm2 += mv[e] * mv[e];
        st += t;     st2 += t * t;
    }
    sm = bredSum256(sm, red);
    sm2 = bredSum256(sm2, red);
    st = bredSum256(st, red);
    st2 = bredSum256(st2, red);
    if (threadIdx.x == 0) {
        rowstats[row * 4 + 0] = sm;
        rowstats[row * 4 + 1] = sm2;
        rowstats[row * 4 + 2] = st;
        rowstats[row * 4 + 3] = st2;
    }
}

// ---------------- per-batch affine constants: t_final = c*t0 + d ----------------
__global__ void bconst_kernel(const float* __restrict__ rowstats, float* __restrict__ consts) {
    __shared__ float red[256];
    const int b = blockIdx.x;
    float s[4] = {0.f, 0.f, 0.f, 0.f};
    for (int r = threadIdx.x; r < SS; r += 256) {
        #pragma unroll
        for (int q = 0; q < 4; q++) s[q] += rowstats[(b * SS + r) * 4 + q];
    }
    #pragma unroll
    for (int q = 0; q < 4; q++) s[q] = bredSum256(s[q], red);
    if (threadIdx.x == 0) {
        const float N = (float)(SS * SS);
        float Sm = s[0], Sm2 = s[1], St = s[2], St2 = s[3];
        float o_mean = Sm / N;
        float o_var = Sm2 / N - o_mean * o_mean;
        float o_std = sqrtf(fmaxf(o_var, 0.01f));
        float e_o = sqrtf(Sm2) + 1e-4f;
        float e_t = sqrtf(St2) + 1e-4f;
        float gamma = fminf(fmaxf(e_o / e_t, 0.8f), 1.2f);
        float tmean = St / N;
        float tvar = gamma * gamma * (St2 / N - tmean * tmean);
        float tstd = sqrtf(fmaxf(tvar, 0.01f));
        float gdyn = fminf(fmaxf(o_std / tstd, 0.8f), 1.2f);
        float c = gdyn * gamma;
        consts[b * 2 + 0] = c;
        consts[b * 2 + 1] = o_mean - c * tmean;
    }
}

// ---------------- final blend + softmax + attn@v, one row per block ----------------
__global__ void attn_kernel(const float* __restrict__ scores, const float* __restrict__ t0,
                            const float* __restrict__ consts, const float* __restrict__ v,
                            float* __restrict__ attnout) {
    __shared__ float p[SS];
    __shared__ float red[128];
    const int idx = blockIdx.x;          // b*H*S + h*S + i
    const int i = idx & (SS - 1);
    const int bh = idx >> 9;
    const int h = bh & 7, b = bh >> 3;
    const int t = threadIdx.x;
    const float* srow = scores + ((size_t)bh * SS + i) * SS;
    const float* trow = t0 + ((size_t)(b * SS) + i) * SS;
    const float c = consts[b * 2], d = consts[b * 2 + 1];

    float loc[4];
    float lmax = -1e30f;
    #pragma unroll
    for (int e = 0; e < 4; e++) {
        int j = t + e * 128;
        float f = srow[j] + 0.1f * fmaf(c, trow[j], d);
        f = fminf(fmaxf(f, -15.f), 15.f);
        loc[e] = f;
        lmax = fmaxf(lmax, f);
    }
    red[t] = lmax; __syncthreads();
    for (int s2 = 64; s2 > 0; s2 >>= 1) {
        if (t < s2) red[t] = fmaxf(red[t], red[t + s2]);
        __syncthreads();
    }
    float rmax = red[0]; __syncthreads();
    float lsum = 0.f;
    #pragma unroll
    for (int e = 0; e < 4; e++) {
        float ex = expf(loc[e] - rmax);
        p[t + e * 128] = ex;
        lsum += ex;
    }
    red[t] = lsum; __syncthreads();
    for (int s2 = 64; s2 > 0; s2 >>= 1) {
        if (t < s2) red[t] += red[t + s2];
        __syncthreads();
    }
    float inv = 1.f / red[0]; __syncthreads();
    #pragma unroll
    for (int e = 0; e < 4; e++) p[t + e * 128] *= inv;
    __syncthreads();

    // attn @ v : 64 head dims, split j range over two halves of the block
    const int dd = t & 63, half = t >> 6;
    const float* vb = v + (size_t)(b * SS) * EE + h * DHH + dd;
    float acc = 0.f;
    const int jbase = half * 256;
    #pragma unroll 8
    for (int j = 0; j < 256; j++) acc = fmaf(p[jbase + j], vb[(size_t)(jbase + j) * EE], acc);
    red[t] = acc; __syncthreads();
    if (half == 0)
        attnout[((size_t)(b * SS) + i) * EE + h * DHH + dd] = red[dd] + red[dd + 64];
}

// ---------------- host ----------------
extern "C" void kernel_launch(void* const* d_in, const int* in_sizes, int n_in,
                              void* d_out, int out_size) {
    const float* x  = (const float*)d_in[0];
    const float* wq = (const float*)d_in[1];
    const float* bq = (const float*)d_in[2];
    const float* wk = (const float*)d_in[3];
    const float* bk = (const float*)d_in[4];
    const float* wv = (const float*)d_in[5];
    const float* bv = (const float*)d_in[6];
    const float* wo = (const float*)d_in[7];
    const float* bo = (const float*)d_in[8];
    const float* w1 = (const float*)d_in[9];
    const float* b1 = (const float*)d_in[10];
    const float* w2 = (const float*)d_in[11];
    const float* b2 = (const float*)d_in[12];
    float* out = (float*)d_out;

    float *q, *k, *v, *scores, *meanb, *t0, *rowstats, *consts, *attnout;
    cudaGetSymbolAddress((void**)&q, g_q);
    cudaGetSymbolAddress((void**)&k, g_k);
    cudaGetSymbolAddress((void**)&v, g_v);
    cudaGetSymbolAddress((void**)&scores, g_scores);
    cudaGetSymbolAddress((void**)&meanb, g_mean);
    cudaGetSymbolAddress((void**)&t0, g_t0);
    cudaGetSymbolAddress((void**)&rowstats, g_rowstats);
    cudaGetSymbolAddress((void**)&consts, g_consts);
    cudaGetSymbolAddress((void**)&attnout, g_attnout);

    dim3 gProj(EE / 64, (BB * SS) / 64);                 // (8, 32)
    gemm_nt64<<<gProj, 256>>>(x, wq, bq, q, BB * SS, EE, EE, 0.125f);  // q * DH^-0.5
    gemm_nt64<<<gProj, 256>>>(x, wk, bk, k, BB * SS, EE, EE, 1.f);
    gemm_nt64<<<gProj, 256>>>(x, wv, bv, v, BB * SS, EE, EE, 1.f);

    dim3 gSc(SS / 64, SS / 64, BB * HH);                 // (8, 8, 32)
    scores_kernel<<<gSc, 256>>>(q, k, scores);

    mean_kernel<<<(BB * SS * SS) / 256, 256>>>(scores, meanb);
    rowtrans_kernel<<<BB * SS, 256>>>(meanb, w1, b1, w2, b2, t0, rowstats);
    bconst_kernel<<<BB, 256>>>(rowstats, consts);
    attn_kernel<<<BB * HH * SS, 128>>>(scores, t0, consts, v, attnout);

    gemm_nt64<<<gProj, 256>>>(attnout, wo, bo, out, BB * SS, EE, EE, 1.f);
}

// round 6
// speedup vs baseline: 1.7340x; 1.7340x over previous
#include <cuda_runtime.h>
#include <math.h>

#define BB   4
#define SS   512
#define EE   512
#define HH   8
#define DHH  64
#define HIDD 128
#define NLUT 4096

typedef unsigned long long ull;

// ---------------- scratch (device globals; no allocation allowed) ----------------
__device__ float g_q[BB * SS * EE];
__device__ float g_k[BB * SS * EE];
__device__ float g_v[BB * SS * EE];
__device__ float g_scores[(size_t)BB * HH * SS * SS];   // clamped scores, then probs in-place
__device__ float g_mean[BB * SS * SS];
__device__ float g_t0[BB * SS * SS];
__device__ float g_rowstats[BB * SS * 4];
__device__ float g_consts[BB * 2];
__device__ float g_attnout[BB * SS * EE];
__device__ float g_lut[NLUT + 8];

// ---------------- packed fp32x2 helpers (Blackwell FFMA2) ----------------
__device__ __forceinline__ ull pack2(float x) {
    ull r; asm("mov.b64 %0, {%1, %1};" : "=l"(r) : "f"(x)); return r;
}
__device__ __forceinline__ void fma2(ull& d, ull a, ull b) {
    asm("fma.rn.f32x2 %0, %1, %2, %0;" : "+l"(d) : "l"(a), "l"(b));
}
__device__ __forceinline__ float2 unpack2(ull v) {
    float2 f; asm("mov.b64 {%0, %1}, %2;" : "=f"(f.x), "=f"(f.y) : "l"(v)); return f;
}

// ---------------- shared GEMM building blocks ----------------
// Tile: 128(m) x 64(n), BK=16, 256 threads, per-thread 8m x 4n as 4 m-pairs (f32x2).
__device__ __forceinline__ void compute16(ull (&acc)[4][4],
                                          const float (*As)[132], const float (*Bs)[68],
                                          int tx, int ty) {
    #pragma unroll
    for (int kk = 0; kk < 16; kk++) {
        ulonglong2 a01 = *(const ulonglong2*)&As[kk][ty * 8];
        ulonglong2 a23 = *(const ulonglong2*)&As[kk][ty * 8 + 4];
        float4 b4 = *(const float4*)&Bs[kk][tx * 4];
        ull a0 = a01.x, a1 = a01.y, a2 = a23.x, a3 = a23.y;
        ull b0 = pack2(b4.x), b1 = pack2(b4.y), b2 = pack2(b4.z), b3 = pack2(b4.w);
        fma2(acc[0][0], a0, b0); fma2(acc[0][1], a0, b1); fma2(acc[0][2], a0, b2); fma2(acc[0][3], a0, b3);
        fma2(acc[1][0], a1, b0); fma2(acc[1][1], a1, b1); fma2(acc[1][2], a1, b2); fma2(acc[1][3], a1, b3);
        fma2(acc[2][0], a2, b0); fma2(acc[2][1], a2, b1); fma2(acc[2][2], a2, b2); fma2(acc[2][3], a2, b3);
        fma2(acc[3][0], a3, b0); fma2(acc[3][1], a3, b1); fma2(acc[3][2], a3, b2); fma2(acc[3][3], a3, b3);
    }
}

__device__ __forceinline__ void load_a128(float (*As)[132], const float* __restrict__ A,
                                          int lda, int m0, int k0, int tid) {
    #pragma unroll
    for (int l = 0; l < 2; l++) {
        int i = tid + (l << 8);
        int r = i >> 2, c4 = (i & 3) << 2;
        float4 t = *(const float4*)&A[(size_t)(m0 + r) * lda + k0 + c4];
        As[c4][r] = t.x; As[c4 + 1][r] = t.y; As[c4 + 2][r] = t.z; As[c4 + 3][r] = t.w;
    }
}
__device__ __forceinline__ void load_b64_nt(float (*Bs)[68], const float* __restrict__ W,
                                            int ldw, int n0, int k0, int tid) {
    int r = tid >> 2, c4 = (tid & 3) << 2;
    float4 t = *(const float4*)&W[(size_t)(n0 + r) * ldw + k0 + c4];
    Bs[c4][r] = t.x; Bs[c4 + 1][r] = t.y; Bs[c4 + 2][r] = t.z; Bs[c4 + 3][r] = t.w;
}

// ---------------- fused QKV projection: C = scale*(x @ W^T + b) ----------------
__global__ __launch_bounds__(256) void qkv_gemm(
    const float* __restrict__ x,
    const float* __restrict__ wq, const float* __restrict__ bq,
    const float* __restrict__ wk, const float* __restrict__ bk,
    const float* __restrict__ wv, const float* __restrict__ bv,
    float* __restrict__ q, float* __restrict__ k, float* __restrict__ v) {
    __shared__ __align__(16) float As[16][132];
    __shared__ __align__(16) float Bs[16][68];
    const int tid = threadIdx.x, tx = tid & 15, ty = tid >> 4;
    const int which = blockIdx.x >> 3;
    const int n0 = (blockIdx.x & 7) << 6;
    const int m0 = blockIdx.y << 7;
    const float* W    = (which == 0) ? wq : (which == 1) ? wk : wv;
    const float* bias = (which == 0) ? bq : (which == 1) ? bk : bv;
    float* C          = (which == 0) ? q  : (which == 1) ? k  : v;
    const float scale = (which == 0) ? 0.125f : 1.0f;

    ull acc[4][4] = {};
    for (int k0 = 0; k0 < EE; k0 += 16) {
        load_a128(As, x, EE, m0, k0, tid);
        load_b64_nt(Bs, W, EE, n0, k0, tid);
        __syncthreads();
        compute16(acc, As, Bs, tx, ty);
        __syncthreads();
    }
    float bn[4];
    #pragma unroll
    for (int j = 0; j < 4; j++) bn[j] = bias[n0 + tx * 4 + j];
    #pragma unroll
    for (int i = 0; i < 4; i++) {
        float2 r[4];
        #pragma unroll
        for (int j = 0; j < 4; j++) r[j] = unpack2(acc[i][j]);
        int m = m0 + ty * 8 + i * 2;
        float4 lo = make_float4(scale * (r[0].x + bn[0]), scale * (r[1].x + bn[1]),
                                scale * (r[2].x + bn[2]), scale * (r[3].x + bn[3]));
        float4 hi = make_float4(scale * (r[0].y + bn[0]), scale * (r[1].y + bn[1]),
                                scale * (r[2].y + bn[2]), scale * (r[3].y + bn[3]));
        *(float4*)&C[(size_t)m * EE + n0 + tx * 4] = lo;
        *(float4*)&C[(size_t)(m + 1) * EE + n0 + tx * 4] = hi;
    }
}

// ---------------- output projection: C = A @ W^T + b ----------------
__global__ __launch_bounds__(256) void out_gemm(
    const float* __restrict__ A, const float* __restrict__ W,
    const float* __restrict__ bias, float* __restrict__ C) {
    __shared__ __align__(16) float As[16][132];
    __shared__ __align__(16) float Bs[16][68];
    const int tid = threadIdx.x, tx = tid & 15, ty = tid >> 4;
    const int n0 = blockIdx.x << 6;
    const int m0 = blockIdx.y << 7;
    ull acc[4][4] = {};
    for (int k0 = 0; k0 < EE; k0 += 16) {
        load_a128(As, A, EE, m0, k0, tid);
        load_b64_nt(Bs, W, EE, n0, k0, tid);
        __syncthreads();
        compute16(acc, As, Bs, tx, ty);
        __syncthreads();
    }
    float bn[4];
    #pragma unroll
    for (int j = 0; j < 4; j++) bn[j] = bias[n0 + tx * 4 + j];
    #pragma unroll
    for (int i = 0; i < 4; i++) {
        float2 r[4];
        #pragma unroll
        for (int j = 0; j < 4; j++) r[j] = unpack2(acc[i][j]);
        int m = m0 + ty * 8 + i * 2;
        float4 lo = make_float4(r[0].x + bn[0], r[1].x + bn[1], r[2].x + bn[2], r[3].x + bn[3]);
        float4 hi = make_float4(r[0].y + bn[0], r[1].y + bn[1], r[2].y + bn[2], r[3].y + bn[3]);
        *(float4*)&C[(size_t)m * EE + n0 + tx * 4] = lo;
        *(float4*)&C[(size_t)(m + 1) * EE + n0 + tx * 4] = hi;
    }
}

// ---------------- scores: clip(q_h @ k_h^T, ±15), per (b,h) ----------------
__global__ __launch_bounds__(256) void scores_gemm(
    const float* __restrict__ q, const float* __restrict__ k, float* __restrict__ scores) {
    __shared__ __align__(16) float As[16][132];
    __shared__ __align__(16) float Bs[16][68];
    const int tid = threadIdx.x, tx = tid & 15, ty = tid >> 4;
    const int bh = blockIdx.z, b = bh >> 3, h = bh & 7;
    const float* A = q + (size_t)(b * SS) * EE + h * DHH;
    const float* B = k + (size_t)(b * SS) * EE + h * DHH;
    const int m0 = blockIdx.y << 7;   // i tile (128)
    const int n0 = blockIdx.x << 6;   // j tile (64)
    ull acc[4][4] = {};
    for (int k0 = 0; k0 < DHH; k0 += 16) {
        load_a128(As, A, EE, m0, k0, tid);
        load_b64_nt(Bs, B, EE, n0, k0, tid);
        __syncthreads();
        compute16(acc, As, Bs, tx, ty);
        __syncthreads();
    }
    float* out = scores + (size_t)bh * SS * SS;
    #pragma unroll
    for (int i = 0; i < 4; i++) {
        float2 r[4];
        #pragma unroll
        for (int j = 0; j < 4; j++) r[j] = unpack2(acc[i][j]);
        int m = m0 + ty * 8 + i * 2;
        float4 lo = make_float4(fminf(fmaxf(r[0].x, -15.f), 15.f), fminf(fmaxf(r[1].x, -15.f), 15.f),
                                fminf(fmaxf(r[2].x, -15.f), 15.f), fminf(fmaxf(r[3].x, -15.f), 15.f));
        float4 hi = make_float4(fminf(fmaxf(r[0].y, -15.f), 15.f), fminf(fmaxf(r[1].y, -15.f), 15.f),
                                fminf(fmaxf(r[2].y, -15.f), 15.f), fminf(fmaxf(r[3].y, -15.f), 15.f));
        *(float4*)&out[(size_t)m * SS + n0 + tx * 4] = lo;
        *(float4*)&out[(size_t)(m + 1) * SS + n0 + tx * 4] = hi;
    }
}

// ---------------- P @ V (NN), per (b,h) ----------------
__global__ __launch_bounds__(256) void pv_gemm(
    const float* __restrict__ P, const float* __restrict__ v, float* __restrict__ outp) {
    __shared__ __align__(16) float As[16][132];
    __shared__ __align__(16) float Bs[16][68];
    const int tid = threadIdx.x, tx = tid & 15, ty = tid >> 4;
    const int bh = blockIdx.z, b = bh >> 3, h = bh & 7;
    const float* A = P + (size_t)bh * SS * SS;
    const int m0 = blockIdx.y << 7;
    ull acc[4][4] = {};
    for (int k0 = 0; k0 < SS; k0 += 16) {
        load_a128(As, A, SS, m0, k0, tid);
        {   // V tile 16(k) x 64(d), direct (no transpose)
            int r = tid >> 4, c4 = (tid & 15) << 2;
            float4 t = *(const float4*)&v[(size_t)(b * SS + k0 + r) * EE + h * DHH + c4];
            *(float4*)&Bs[r][c4] = t;
        }
        __syncthreads();
        compute16(acc, As, Bs, tx, ty);
        __syncthreads();
    }
    #pragma unroll
    for (int i = 0; i < 4; i++) {
        float2 r[4];
        #pragma unroll
        for (int j = 0; j < 4; j++) r[j] = unpack2(acc[i][j]);
        int m = m0 + ty * 8 + i * 2;
        float4 lo = make_float4(r[0].x, r[1].x, r[2].x, r[3].x);
        float4 hi = make_float4(r[0].y, r[1].y, r[2].y, r[3].y);
        *(float4*)&outp[(size_t)(b * SS + m) * EE + h * DHH + tx * 4] = lo;
        *(float4*)&outp[(size_t)(b * SS + m + 1) * EE + h * DHH + tx * 4] = hi;
    }
}

// ---------------- head mean (float4) ----------------
__global__ void mean_kernel(const float4* __restrict__ sc, float4* __restrict__ mb) {
    int idx = blockIdx.x * 256 + threadIdx.x;      // over B * (S*S/4)
    int b = idx >> 16, r = idx & 65535;
    const float4* p = sc + (size_t)b * (HH * 65536) + r;
    float4 s = p[0];
    #pragma unroll
    for (int h = 1; h < HH; h++) {
        float4 t = p[(size_t)h * 65536];
        s.x += t.x; s.y += t.y; s.z += t.z; s.w += t.w;
    }
    const float inv = 1.f / HH;
    s.x *= inv; s.y *= inv; s.z *= inv; s.w *= inv;
    mb[idx] = s;
}

// ---------------- LUT: sigmoid(taylor(auto(s))) as function of mean value ----------------
__global__ void lut_kernel(const float* __restrict__ w1, const float* __restrict__ b1,
                           const float* __restrict__ w2, const float* __restrict__ b2,
                           float* __restrict__ lut) {
    int i = blockIdx.x * blockDim.x + threadIdx.x;
    if (i > NLUT) return;
    float mm = -8.f + (float)i * (16.f / NLUT);
    float s = mm * 0.05f;
    float a = b2[0];
    for (int h2 = 0; h2 < HIDD; h2++) {
        float hid = fmaf(s, w1[h2], b1[h2]);
        hid = fminf(fmaxf(hid, 0.f), 5.f);   // relu(clip(x,-5,5))
        a = fmaf(hid, w2[h2], a);
    }
    a = fminf(fmaxf(a, -5.f), 5.f);
    float tay = fminf(fmaxf(fmaf(2.5f, a, 1.f), 0.5f), 1.5f);
    lut[i] = 1.f / (1.f + expf(-tay));
}

// ---------------- block reductions ----------------
__device__ __forceinline__ float bredMax256(float v, float* red) {
    int t = threadIdx.x;
    red[t] = v; __syncthreads();
    for (int s = 128; s > 0; s >>= 1) {
        if (t < s) red[t] = fmaxf(red[t], red[t + s]);
        __syncthreads();
    }
    float r = red[0]; __syncthreads();
    return r;
}
__device__ __forceinline__ float bredSum256(float v, float* red) {
    int t = threadIdx.x;
    red[t] = v; __syncthreads();
    for (int s = 128; s > 0; s >>= 1) {
        if (t < s) red[t] += red[t + s];
        __syncthreads();
    }
    float r = red[0]; __syncthreads();
    return r;
}

// ---------------- per-row transform -> t0, row stats (LUT-based) ----------------
__global__ __launch_bounds__(256) void rowtrans_kernel(
    const float* __restrict__ meanb, const float* __restrict__ lut,
    float* __restrict__ t0, float* __restrict__ rowstats) {
    __shared__ float red[256];
    const int row = blockIdx.x;
    const float* m = meanb + (size_t)row * SS;
    const int t = threadIdx.x;

    float2 mv2 = *(const float2*)&m[t * 2];
    float mv[2] = {mv2.x, mv2.y};
    float sg[2], pv[2], hv[2];
    float lmax = -1e30f;
    #pragma unroll
    for (int e = 0; e < 2; e++) {
        float mm = mv[e];
        float u = (fminf(fmaxf(mm, -8.f), 8.f) + 8.f) * (NLUT / 16.f);
        int i0 = min((int)u, NLUT - 1);
        float fr = u - (float)i0;
        float l0 = lut[i0];
        sg[e] = l0 + fr * (lut[i0 + 1] - l0);
        float xc = fminf(fmaxf(mm, -10.f), 10.f);
        pv[e] = xc;
        lmax = fmaxf(lmax, xc);
    }
    float rmax = bredMax256(lmax, red);
    float lsum = 0.f;
    #pragma unroll
    for (int e = 0; e < 2; e++) { pv[e] = expf(pv[e] - rmax); lsum += pv[e]; }
    float rsum = bredSum256(lsum, red);
    float inv = 1.f / rsum;
    float hmax = -1e30f;
    #pragma unroll
    for (int e = 0; e < 2; e++) {
        float p = pv[e] * inv;
        hv[e] = 3.f * (-p * logf(p + 1e-6f));
        hmax = fmaxf(hmax, hv[e]);
    }
    float rhmax = bredMax256(hmax, red);
    lsum = 0.f;
    #pragma unroll
    for (int e = 0; e < 2; e++) { hv[e] = expf(hv[e] - rhmax); lsum += hv[e]; }
    float rhsum = bredSum256(lsum, red);
    float inv2 = 1.f / rhsum;

    float sm = 0.f, sm2 = 0.f, st = 0.f, st2 = 0.f;
    float tv[2];
    #pragma unroll
    for (int e = 0; e < 2; e++) {
        float tt = sg[e] * hv[e] * inv2;
        tv[e] = tt;
        sm += mv[e]; sm2 += mv[e] * mv[e];
        st += tt;    st2 += tt * tt;
    }
    *(float2*)&t0[(size_t)row * SS + t * 2] = make_float2(tv[0], tv[1]);
    sm  = bredSum256(sm, red);
    sm2 = bredSum256(sm2, red);
    st  = bredSum256(st, red);
    st2 = bredSum256(st2, red);
    if (t == 0) {
        rowstats[row * 4 + 0] = sm;
        rowstats[row * 4 + 1] = sm2;
        rowstats[row * 4 + 2] = st;
        rowstats[row * 4 + 3] = st2;
    }
}

// ---------------- per-batch affine constants: t_final = c*t0 + d ----------------
__global__ void bconst_kernel(const float* __restrict__ rowstats, float* __restrict__ consts) {
    __shared__ float red[256];
    const int b = blockIdx.x;
    float s[4] = {0.f, 0.f, 0.f, 0.f};
    for (int r = threadIdx.x; r < SS; r += 256) {
        #pragma unroll
        for (int q = 0; q < 4; q++) s[q] += rowstats[(b * SS + r) * 4 + q];
    }
    #pragma unroll
    for (int q = 0; q < 4; q++) s[q] = bredSum256(s[q], red);
    if (threadIdx.x == 0) {
        const float N = (float)(SS * SS);
        float Sm = s[0], Sm2 = s[1], St = s[2], St2 = s[3];
        float o_mean = Sm / N;
        float o_var = Sm2 / N - o_mean * o_mean;
        float o_std = sqrtf(fmaxf(o_var, 0.01f));
        float e_o = sqrtf(Sm2) + 1e-4f;
        float e_t = sqrtf(St2) + 1e-4f;
        float gamma = fminf(fmaxf(e_o / e_t, 0.8f), 1.2f);
        float tmean = St / N;
        float tvar = gamma * gamma * (St2 / N - tmean * tmean);
        float tstd = sqrtf(fmaxf(tvar, 0.01f));
        float gdyn = fminf(fmaxf(o_std / tstd, 0.8f), 1.2f);
        float c = gdyn * gamma;
        consts[b * 2 + 0] = c;
        consts[b * 2 + 1] = o_mean - c * tmean;
    }
}

// ---------------- blend + softmax in-place on scores ----------------
__global__ __launch_bounds__(128) void probs_kernel(
    float* __restrict__ sc, const float* __restrict__ t0, const float* __restrict__ consts) {
    __shared__ float red[128];
    const int idx = blockIdx.x;          // b*H*S + h*S + i
    const int i = idx & (SS - 1);
    const int bh = idx >> 9;
    const int b = bh >> 3;
    float* srow = sc + ((size_t)bh * SS + i) * SS;
    const float* trow = t0 + ((size_t)(b * SS) + i) * SS;
    const float c = consts[b * 2], d = consts[b * 2 + 1];
    const int t = threadIdx.x;

    float4 s4 = *(float4*)&srow[t * 4];
    float4 t4 = *(const float4*)&trow[t * 4];
    float f[4];
    f[0] = fminf(fmaxf(s4.x + 0.1f * fmaf(c, t4.x, d), -15.f), 15.f);
    f[1] = fminf(fmaxf(s4.y + 0.1f * fmaf(c, t4.y, d), -15.f), 15.f);
    f[2] = fminf(fmaxf(s4.z + 0.1f * fmaf(c, t4.z, d), -15.f), 15.f);
    f[3] = fminf(fmaxf(s4.w + 0.1f * fmaf(c, t4.w, d), -15.f), 15.f);
    float lmax = fmaxf(fmaxf(f[0], f[1]), fmaxf(f[2], f[3]));
    red[t] = lmax; __syncthreads();
    for (int s2 = 64; s2 > 0; s2 >>= 1) {
        if (t < s2) red[t] = fmaxf(red[t], red[t + s2]);
        __syncthreads();
    }
    float rmax = red[0]; __syncthreads();
    float lsum = 0.f;
    #pragma unroll
    for (int e = 0; e < 4; e++) { f[e] = expf(f[e] - rmax); lsum += f[e]; }
    red[t] = lsum; __syncthreads();
    for (int s2 = 64; s2 > 0; s2 >>= 1) {
        if (t < s2) red[t] += red[t + s2];
        __syncthreads();
    }
    float inv = 1.f / red[0];
    *(float4*)&srow[t * 4] = make_float4(f[0] * inv, f[1] * inv, f[2] * inv, f[3] * inv);
}

// ---------------- host ----------------
extern "C" void kernel_launch(void* const* d_in, const int* in_sizes, int n_in,
                              void* d_out, int out_size) {
    const float* x  = (const float*)d_in[0];
    const float* wq = (const float*)d_in[1];
    const float* bq = (const float*)d_in[2];
    const float* wk = (const float*)d_in[3];
    const float* bk = (const float*)d_in[4];
    const float* wv = (const float*)d_in[5];
    const float* bv = (const float*)d_in[6];
    const float* wo = (const float*)d_in[7];
    const float* bo = (const float*)d_in[8];
    const float* w1 = (const float*)d_in[9];
    const float* b1 = (const float*)d_in[10];
    const float* w2 = (const float*)d_in[11];
    const float* b2 = (const float*)d_in[12];
    float* out = (float*)d_out;

    float *q, *k, *v, *scores, *meanb, *t0, *rowstats, *consts, *attnout, *lut;
    cudaGetSymbolAddress((void**)&q, g_q);
    cudaGetSymbolAddress((void**)&k, g_k);
    cudaGetSymbolAddress((void**)&v, g_v);
    cudaGetSymbolAddress((void**)&scores, g_scores);
    cudaGetSymbolAddress((void**)&meanb, g_mean);
    cudaGetSymbolAddress((void**)&t0, g_t0);
    cudaGetSymbolAddress((void**)&rowstats, g_rowstats);
    cudaGetSymbolAddress((void**)&consts, g_consts);
    cudaGetSymbolAddress((void**)&attnout, g_attnout);
    cudaGetSymbolAddress((void**)&lut, g_lut);

    lut_kernel<<<17, 256>>>(w1, b1, w2, b2, lut);

    qkv_gemm<<<dim3(24, 16), 256>>>(x, wq, bq, wk, bk, wv, bv, q, k, v);

    scores_gemm<<<dim3(8, 4, 32), 256>>>(q, k, scores);

    mean_kernel<<<1024, 256>>>((const float4*)scores, (float4*)meanb);
    rowtrans_kernel<<<BB * SS, 256>>>(meanb, lut, t0, rowstats);
    bconst_kernel<<<BB, 256>>>(rowstats, consts);
    probs_kernel<<<BB * HH * SS, 128>>>(scores, t0, consts);

    pv_gemm<<<dim3(1, 4, 32), 256>>>(scores, v, attnout);

    out_gemm<<<dim3(8, 16), 256>>>(attnout, wo, bo, out);
}

// round 14
// speedup vs baseline: 2.0157x; 1.1625x over previous
#include <cuda_runtime.h>
#include <cuda_bf16.h>
#include <mma.h>
#include <cstdint>
#include <stdint.h>
#include <math.h>

using namespace nvcuda;

#define BB   4
#define SS   512
#define EE   512
#define HH   8
#define DHH  64
#define HIDD 128
#define NLUT 4096

typedef unsigned long long ull;

// ---------------- scratch (device globals; no allocation allowed) ----------------
__device__ float g_q[BB * SS * EE];
__device__ float g_k[BB * SS * EE];
__device__ float g_v[BB * SS * EE];
__device__ float g_scores[(size_t)BB * HH * SS * SS];   // clamped scores, then probs in-place
__device__ float g_mean[BB * SS * SS];
__device__ float g_t0[BB * SS * SS];
__device__ float g_rowstats[BB * SS * 4];
__device__ float g_consts[BB * 2];
__device__ float g_attnout[BB * SS * EE];
__device__ float g_lut[NLUT + 8];
// bf16 hi/lo splits
__device__ __nv_bfloat16 g_xhi[BB * SS * EE], g_xlo[BB * SS * EE];
__device__ __nv_bfloat16 g_wqhi[EE * EE], g_wqlo[EE * EE];
__device__ __nv_bfloat16 g_wkhi[EE * EE], g_wklo[EE * EE];
__device__ __nv_bfloat16 g_wvhi[EE * EE], g_wvlo[EE * EE];
__device__ __nv_bfloat16 g_wohi[EE * EE], g_wolo[EE * EE];
__device__ __nv_bfloat16 g_aohi[BB * SS * EE], g_aolo[BB * SS * EE];

// ---------------- packed fp32x2 helpers (Blackwell FFMA2) ----------------
__device__ __forceinline__ ull pack2(float x) {
    ull r; asm("mov.b64 %0, {%1, %1};" : "=l"(r) : "f"(x)); return r;
}
__device__ __forceinline__ void fma2(ull& d, ull a, ull b) {
    asm("fma.rn.f32x2 %0, %1, %2, %0;" : "+l"(d) : "l"(a), "l"(b));
}
__device__ __forceinline__ float2 unpack2(ull v) {
    float2 f; asm("mov.b64 {%0, %1}, %2;" : "=f"(f.x), "=f"(f.y) : "l"(v)); return f;
}

// ---------------- wmma bf16x3 GEMM: C[128x64 tile] = scale*(A @ W^T + bias) ----------------
// A: MxK fp32 split into (Ahi,Alo) bf16 row-major; W: NxK split. K=512.
// 256 threads = 8 warps; warp (wm, wn) computes 32x32 via 2x2 wmma 16x16x16 frags.
// Smem tiles padded to 40 bf16 per row (80B stride) for bank rotation.
#define HG_LDS 40
#define HG_A_BYTES (128 * HG_LDS * 2)          // 10240
#define HG_B_BYTES (64 * HG_LDS * 2)           // 5120
#define HG_SMEM (2 * HG_A_BYTES + 2 * HG_B_BYTES)  // 30720

__device__ __forceinline__ void hgemm_core(
    const __nv_bfloat16* __restrict__ Ahi, const __nv_bfloat16* __restrict__ Alo,
    const __nv_bfloat16* __restrict__ Whi, const __nv_bfloat16* __restrict__ Wlo,
    const float* __restrict__ bias, float* __restrict__ C, float scale,
    int m0, int n0) {
    __shared__ __align__(16) char sm[HG_SMEM];
    __nv_bfloat16 (*Ah)[HG_LDS] = (__nv_bfloat16(*)[HG_LDS])(sm);
    __nv_bfloat16 (*Al)[HG_LDS] = (__nv_bfloat16(*)[HG_LDS])(sm + HG_A_BYTES);
    __nv_bfloat16 (*Bh)[HG_LDS] = (__nv_bfloat16(*)[HG_LDS])(sm + 2 * HG_A_BYTES);
    __nv_bfloat16 (*Bl)[HG_LDS] = (__nv_bfloat16(*)[HG_LDS])(sm + 2 * HG_A_BYTES + HG_B_BYTES);

    const int tid = threadIdx.x;
    const int warp = tid >> 5, lane = tid & 31;
    const int wm = warp & 3, wn = warp >> 2;     // 4 m-groups x 2 n-groups

    wmma::fragment<wmma::accumulator, 16, 16, 16, float> acc[2][2];
    #pragma unroll
    for (int i = 0; i < 2; i++)
        #pragma unroll
        for (int j = 0; j < 2; j++) wmma::fill_fragment(acc[i][j], 0.0f);

    for (int kc = 0; kc < EE; kc += 32) {
        // stage A (128x32 hi+lo) and B (64x32 hi+lo)
        #pragma unroll
        for (int l = 0; l < 2; l++) {
            int idx = tid + (l << 8);            // 0..511
            int row = idx >> 2, c8 = (idx & 3) << 3;
            size_t gi = (size_t)(m0 + row) * EE + kc + c8;
            *(uint4*)&Ah[row][c8] = *(const uint4*)(Ahi + gi);
            *(uint4*)&Al[row][c8] = *(const uint4*)(Alo + gi);
        }
        {
            int row = tid >> 2, c8 = (tid & 3) << 3;
            size_t gi = (size_t)(n0 + row) * EE + kc + c8;
            *(uint4*)&Bh[row][c8] = *(const uint4*)(Whi + gi);
            *(uint4*)&Bl[row][c8] = *(const uint4*)(Wlo + gi);
        }
        __syncthreads();

        #pragma unroll
        for (int ks = 0; ks < 2; ks++) {
            const int k8 = ks << 4;
            wmma::fragment<wmma::matrix_a, 16, 16, 16, __nv_bfloat16, wmma::row_major> ah[2], al[2];
            wmma::fragment<wmma::matrix_b, 16, 16, 16, __nv_bfloat16, wmma::col_major> bh[2], bl[2];
            #pragma unroll
            for (int i = 0; i < 2; i++) {
                wmma::load_matrix_sync(ah[i], &Ah[wm * 32 + i * 16][k8], HG_LDS);
                wmma::load_matrix_sync(al[i], &Al[wm * 32 + i * 16][k8], HG_LDS);
            }
            #pragma unroll
            for (int j = 0; j < 2; j++) {
                wmma::load_matrix_sync(bh[j], &Bh[wn * 32 + j * 16][k8], HG_LDS);
                wmma::load_matrix_sync(bl[j], &Bl[wn * 32 + j * 16][k8], HG_LDS);
            }
            #pragma unroll
            for (int i = 0; i < 2; i++)
                #pragma unroll
                for (int j = 0; j < 2; j++) {
                    wmma::mma_sync(acc[i][j], ah[i], bh[j], acc[i][j]);
                    wmma::mma_sync(acc[i][j], ah[i], bl[j], acc[i][j]);
                    wmma::mma_sync(acc[i][j], al[i], bh[j], acc[i][j]);
                }
        }
        __syncthreads();
    }

    // epilogue: stage each 16x16 tile through smem, add bias, scale, store
    float* ebuf = (float*)(sm) + warp * (16 * 20);
    const int r = lane >> 1, c0 = (lane & 1) << 3;
    #pragma unroll
    for (int i = 0; i < 2; i++)
        #pragma unroll
        for (int j = 0; j < 2; j++) {
            wmma::store_matrix_sync(ebuf, acc[i][j], 20, wmma::mem_row_major);
            __syncwarp();
            int gm = m0 + wm * 32 + i * 16 + r;
            int gn = n0 + wn * 32 + j * 16 + c0;
            float4 b0 = *(const float4*)&bias[gn];
            float4 b1 = *(const float4*)&bias[gn + 4];
            const float* e = ebuf + r * 20 + c0;
            float4 o0 = make_float4(scale * (e[0] + b0.x), scale * (e[1] + b0.y),
                                    scale * (e[2] + b0.z), scale * (e[3] + b0.w));
            float4 o1 = make_float4(scale * (e[4] + b1.x), scale * (e[5] + b1.y),
                                    scale * (e[6] + b1.z), scale * (e[7] + b1.w));
            *(float4*)&C[(size_t)gm * EE + gn] = o0;
            *(float4*)&C[(size_t)gm * EE + gn + 4] = o1;
            __syncwarp();
        }
}

__global__ __launch_bounds__(256, 2) void hqkv_gemm(
    const __nv_bfloat16* __restrict__ xhi, const __nv_bfloat16* __restrict__ xlo,
    const __nv_bfloat16* __restrict__ qh, const __nv_bfloat16* __restrict__ ql, const float* __restrict__ bq,
    const __nv_bfloat16* __restrict__ kh, const __nv_bfloat16* __restrict__ kl, const float* __restrict__ bk,
    const __nv_bfloat16* __restrict__ vh, const __nv_bfloat16* __restrict__ vl, const float* __restrict__ bv,
    float* __restrict__ q, float* __restrict__ k, float* __restrict__ v) {
    const int w = blockIdx.z;
    const __nv_bfloat16* Whi = (w == 0) ? qh : (w == 1) ? kh : vh;
    const __nv_bfloat16* Wlo = (w == 0) ? ql : (w == 1) ? kl : vl;
    const float* bias = (w == 0) ? bq : (w == 1) ? bk : bv;
    float* C = (w == 0) ? q : (w == 1) ? k : v;
    hgemm_core(xhi, xlo, Whi, Wlo, bias, C, (w == 0) ? 0.125f : 1.0f,
               blockIdx.y << 7, blockIdx.x << 6);
}

__global__ __launch_bounds__(256, 2) void hout_gemm(
    const __nv_bfloat16* __restrict__ ahi, const __nv_bfloat16* __restrict__ alo,
    const __nv_bfloat16* __restrict__ whi, const __nv_bfloat16* __restrict__ wlo,
    const float* __restrict__ bias, float* __restrict__ C) {
    hgemm_core(ahi, alo, whi, wlo, bias, C, 1.0f, blockIdx.y << 7, blockIdx.x << 6);
}

// ---------------- fp32 -> bf16 hi/lo split ----------------
__global__ __launch_bounds__(256) void cvt_kernel(const float* __restrict__ src,
                                                  __nv_bfloat16* __restrict__ hi,
                                                  __nv_bfloat16* __restrict__ lo) {
    int i = (blockIdx.x * 256 + threadIdx.x) * 8;
    float4 a = *(const float4*)&src[i];
    float4 b = *(const float4*)&src[i + 4];
    float f[8] = {a.x, a.y, a.z, a.w, b.x, b.y, b.z, b.w};
    __nv_bfloat16 h[8], l[8];
    #pragma unroll
    for (int j = 0; j < 8; j++) {
        h[j] = __float2bfloat16(f[j]);
        l[j] = __float2bfloat16(f[j] - __bfloat162float(h[j]));
    }
    *(uint4*)&hi[i] = *(uint4*)h;
    *(uint4*)&lo[i] = *(uint4*)l;
}

// ---------------- FFMA2 GEMM building blocks (scores / PV) ----------------
__device__ __forceinline__ void compute16(ull (&acc)[4][4],
                                          const float (*As)[132], const float (*Bs)[68],
                                          int tx, int ty) {
    #pragma unroll
    for (int kk = 0; kk < 16; kk++) {
        ulonglong2 a01 = *(const ulonglong2*)&As[kk][ty * 8];
        ulonglong2 a23 = *(const ulonglong2*)&As[kk][ty * 8 + 4];
        float4 b4 = *(const float4*)&Bs[kk][tx * 4];
        ull a0 = a01.x, a1 = a01.y, a2 = a23.x, a3 = a23.y;
        ull b0 = pack2(b4.x), b1 = pack2(b4.y), b2 = pack2(b4.z), b3 = pack2(b4.w);
        fma2(acc[0][0], a0, b0); fma2(acc[0][1], a0, b1); fma2(acc[0][2], a0, b2); fma2(acc[0][3], a0, b3);
        fma2(acc[1][0], a1, b0); fma2(acc[1][1], a1, b1); fma2(acc[1][2], a1, b2); fma2(acc[1][3], a1, b3);
        fma2(acc[2][0], a2, b0); fma2(acc[2][1], a2, b1); fma2(acc[2][2], a2, b2); fma2(acc[2][3], a2, b3);
        fma2(acc[3][0], a3, b0); fma2(acc[3][1], a3, b1); fma2(acc[3][2], a3, b2); fma2(acc[3][3], a3, b3);
    }
}
__device__ __forceinline__ void load_a128(float (*As)[132], const float* __restrict__ A,
                                          int lda, int m0, int k0, int tid) {
    #pragma unroll
    for (int l = 0; l < 2; l++) {
        int i = tid + (l << 8);
        int r = i >> 2, c4 = (i & 3) << 2;
        float4 t = *(const float4*)&A[(size_t)(m0 + r) * lda + k0 + c4];
        As[c4][r] = t.x; As[c4 + 1][r] = t.y; As[c4 + 2][r] = t.z; As[c4 + 3][r] = t.w;
    }
}
__device__ __forceinline__ void load_b64_nt(float (*Bs)[68], const float* __restrict__ W,
                                            int ldw, int n0, int k0, int tid) {
    int r = tid >> 2, c4 = (tid & 3) << 2;
    float4 t = *(const float4*)&W[(size_t)(n0 + r) * ldw + k0 + c4];
    Bs[c4][r] = t.x; Bs[c4 + 1][r] = t.y; Bs[c4 + 2][r] = t.z; Bs[c4 + 3][r] = t.w;
}

// ---------------- scores: clip(q_h @ k_h^T, ±15), per (b,h) ----------------
__global__ __launch_bounds__(256) void scores_gemm(
    const float* __restrict__ q, const float* __restrict__ k, float* __restrict__ scores) {
    __shared__ __align__(16) float As[16][132];
    __shared__ __align__(16) float Bs[16][68];
    const int tid = threadIdx.x, tx = tid & 15, ty = tid >> 4;
    const int bh = blockIdx.z, b = bh >> 3, h = bh & 7;
    const float* A = q + (size_t)(b * SS) * EE + h * DHH;
    const float* B = k + (size_t)(b * SS) * EE + h * DHH;
    const int m0 = blockIdx.y << 7;
    const int n0 = blockIdx.x << 6;
    ull acc[4][4] = {};
    for (int k0 = 0; k0 < DHH; k0 += 16) {
        load_a128(As, A, EE, m0, k0, tid);
        load_b64_nt(Bs, B, EE, n0, k0, tid);
        __syncthreads();
        compute16(acc, As, Bs, tx, ty);
        __syncthreads();
    }
    float* out = scores + (size_t)bh * SS * SS;
    #pragma unroll
    for (int i = 0; i < 4; i++) {
        float2 r[4];
        #pragma unroll
        for (int j = 0; j < 4; j++) r[j] = unpack2(acc[i][j]);
        int m = m0 + ty * 8 + i * 2;
        float4 lo = make_float4(fminf(fmaxf(r[0].x, -15.f), 15.f), fminf(fmaxf(r[1].x, -15.f), 15.f),
                                fminf(fmaxf(r[2].x, -15.f), 15.f), fminf(fmaxf(r[3].x, -15.f), 15.f));
        float4 hi = make_float4(fminf(fmaxf(r[0].y, -15.f), 15.f), fminf(fmaxf(r[1].y, -15.f), 15.f),
                                fminf(fmaxf(r[2].y, -15.f), 15.f), fminf(fmaxf(r[3].y, -15.f), 15.f));
        *(float4*)&out[(size_t)m * SS + n0 + tx * 4] = lo;
        *(float4*)&out[(size_t)(m + 1) * SS + n0 + tx * 4] = hi;
    }
}

// ---------------- P @ V (NN), per (b,h) ----------------
__global__ __launch_bounds__(256) void pv_gemm(
    const float* __restrict__ P, const float* __restrict__ v, float* __restrict__ outp) {
    __shared__ __align__(16) float As[16][132];
    __shared__ __align__(16) float Bs[16][68];
    const int tid = threadIdx.x, tx = tid & 15, ty = tid >> 4;
    const int bh = blockIdx.z, b = bh >> 3, h = bh & 7;
    const float* A = P + (size_t)bh * SS * SS;
    const int m0 = blockIdx.y << 7;
    ull acc[4][4] = {};
    for (int k0 = 0; k0 < SS; k0 += 16) {
        load_a128(As, A, SS, m0, k0, tid);
        {
            int r = tid >> 4, c4 = (tid & 15) << 2;
            float4 t = *(const float4*)&v[(size_t)(b * SS + k0 + r) * EE + h * DHH + c4];
            *(float4*)&Bs[r][c4] = t;
        }
        __syncthreads();
        compute16(acc, As, Bs, tx, ty);
        __syncthreads();
    }
    #pragma unroll
    for (int i = 0; i < 4; i++) {
        float2 r[4];
        #pragma unroll
        for (int j = 0; j < 4; j++) r[j] = unpack2(acc[i][j]);
        int m = m0 + ty * 8 + i * 2;
        float4 lo = make_float4(r[0].x, r[1].x, r[2].x, r[3].x);
        float4 hi = make_float4(r[0].y, r[1].y, r[2].y, r[3].y);
        *(float4*)&outp[(size_t)(b * SS + m) * EE + h * DHH + tx * 4] = lo;
        *(float4*)&outp[(size_t)(b * SS + m + 1) * EE + h * DHH + tx * 4] = hi;
    }
}

// ---------------- head mean (float4) ----------------
__global__ void mean_kernel(const float4* __restrict__ sc, float4* __restrict__ mb) {
    int idx = blockIdx.x * 256 + threadIdx.x;
    int b = idx >> 16, r = idx & 65535;
    const float4* p = sc + (size_t)b * (HH * 65536) + r;
    float4 s = p[0];
    #pragma unroll
    for (int h = 1; h < HH; h++) {
        float4 t = p[(size_t)h * 65536];
        s.x += t.x; s.y += t.y; s.z += t.z; s.w += t.w;
    }
    const float inv = 1.f / HH;
    s.x *= inv; s.y *= inv; s.z *= inv; s.w *= inv;
    mb[idx] = s;
}

// ---------------- LUT: sigmoid(taylor(auto(s))) ----------------
__global__ void lut_kernel(const float* __restrict__ w1, const float* __restrict__ b1,
                           const float* __restrict__ w2, const float* __restrict__ b2,
                           float* __restrict__ lut) {
    int i = blockIdx.x * blockDim.x + threadIdx.x;
    if (i > NLUT) return;
    float mm = -8.f + (float)i * (16.f / NLUT);
    float s = mm * 0.05f;
    float a = b2[0];
    for (int h2 = 0; h2 < HIDD; h2++) {
        float hid = fmaf(s, w1[h2], b1[h2]);
        hid = fminf(fmaxf(hid, 0.f), 5.f);
        a = fmaf(hid, w2[h2], a);
    }
    a = fminf(fmaxf(a, -5.f), 5.f);
    float tay = fminf(fmaxf(fmaf(2.5f, a, 1.f), 0.5f), 1.5f);
    lut[i] = 1.f / (1.f + expf(-tay));
}

// ---------------- block reductions ----------------
__device__ __forceinline__ float bredMax256(float v, float* red) {
    int t = threadIdx.x;
    red[t] = v; __syncthreads();
    for (int s = 128; s > 0; s >>= 1) {
        if (t < s) red[t] = fmaxf(red[t], red[t + s]);
        __syncthreads();
    }
    float r = red[0]; __syncthreads();
    return r;
}
__device__ __forceinline__ float bredSum256(float v, float* red) {
    int t = threadIdx.x;
    red[t] = v; __syncthreads();
    for (int s = 128; s > 0; s >>= 1) {
        if (t < s) red[t] += red[t + s];
        __syncthreads();
    }
    float r = red[0]; __syncthreads();
    return r;
}

// ---------------- per-row transform -> t0, row stats ----------------
__global__ __launch_bounds__(256) void rowtrans_kernel(
    const float* __restrict__ meanb, const float* __restrict__ lut,
    float* __restrict__ t0, float* __restrict__ rowstats) {
    __shared__ float red[256];
    const int row = blockIdx.x;
    const float* m = meanb + (size_t)row * SS;
    const int t = threadIdx.x;

    float2 mv2 = *(const float2*)&m[t * 2];
    float mv[2] = {mv2.x, mv2.y};
    float sg[2], pv[2], hv[2];
    float lmax = -1e30f;
    #pragma unroll
    for (int e = 0; e < 2; e++) {
        float mm = mv[e];
        float u = (fminf(fmaxf(mm, -8.f), 8.f) + 8.f) * (NLUT / 16.f);
        int i0 = min((int)u, NLUT - 1);
        float fr = u - (float)i0;
        float l0 = lut[i0];
        sg[e] = l0 + fr * (lut[i0 + 1] - l0);
        float xc = fminf(fmaxf(mm, -10.f), 10.f);
        pv[e] = xc;
        lmax = fmaxf(lmax, xc);
    }
    float rmax = bredMax256(lmax, red);
    float lsum = 0.f;
    #pragma unroll
    for (int e = 0; e < 2; e++) { pv[e] = expf(pv[e] - rmax); lsum += pv[e]; }
    float rsum = bredSum256(lsum, red);
    float inv = 1.f / rsum;
    float hmax = -1e30f;
    #pragma unroll
    for (int e = 0; e < 2; e++) {
        float p = pv[e] * inv;
        hv[e] = 3.f * (-p * logf(p + 1e-6f));
        hmax = fmaxf(hmax, hv[e]);
    }
    float rhmax = bredMax256(hmax, red);
    lsum = 0.f;
    #pragma unroll
    for (int e = 0; e < 2; e++) { hv[e] = expf(hv[e] - rhmax); lsum += hv[e]; }
    float rhsum = bredSum256(lsum, red);
    float inv2 = 1.f / rhsum;

    float sm = 0.f, sm2 = 0.f, st = 0.f, st2 = 0.f;
    float tv[2];
    #pragma unroll
    for (int e = 0; e < 2; e++) {
        float tt = sg[e] * hv[e] * inv2;
        tv[e] = tt;
        sm += mv[e]; sm2 += mv[e] * mv[e];
        st += tt;    st2 += tt * tt;
    }
    *(float2*)&t0[(size_t)row * SS + t * 2] = make_float2(tv[0], tv[1]);
    sm  = bredSum256(sm, red);
    sm2 = bredSum256(sm2, red);
    st  = bredSum256(st, red);
    st2 = bredSum256(st2, red);
    if (t == 0) {
        rowstats[row * 4 + 0] = sm;
        rowstats[row * 4 + 1] = sm2;
        rowstats[row * 4 + 2] = st;
        rowstats[row * 4 + 3] = st2;
    }
}

// ---------------- per-batch affine constants ----------------
__global__ void bconst_kernel(const float* __restrict__ rowstats, float* __restrict__ consts) {
    __shared__ float red[256];
    const int b = blockIdx.x;
    float s[4] = {0.f, 0.f, 0.f, 0.f};
    for (int r = threadIdx.x; r < SS; r += 256) {
        #pragma unroll
        for (int q = 0; q < 4; q++) s[q] += rowstats[(b * SS + r) * 4 + q];
    }
    #pragma unroll
    for (int q = 0; q < 4; q++) s[q] = bredSum256(s[q], red);
    if (threadIdx.x == 0) {
        const float N = (float)(SS * SS);
        float Sm = s[0], Sm2 = s[1], St = s[2], St2 = s[3];
        float o_mean = Sm / N;
        float o_var = Sm2 / N - o_mean * o_mean;
        float o_std = sqrtf(fmaxf(o_var, 0.01f));
        float e_o = sqrtf(Sm2) + 1e-4f;
        float e_t = sqrtf(St2) + 1e-4f;
        float gamma = fminf(fmaxf(e_o / e_t, 0.8f), 1.2f);
        float tmean = St / N;
        float tvar = gamma * gamma * (St2 / N - tmean * tmean);
        float tstd = sqrtf(fmaxf(tvar, 0.01f));
        float gdyn = fminf(fmaxf(o_std / tstd, 0.8f), 1.2f);
        float c = gdyn * gamma;
        consts[b * 2 + 0] = c;
        consts[b * 2 + 1] = o_mean - c * tmean;
    }
}

// ---------------- blend + softmax in-place on scores ----------------
__global__ __launch_bounds__(128) void probs_kernel(
    float* __restrict__ sc, const float* __restrict__ t0, const float* __restrict__ consts) {
    __shared__ float red[128];
    const int idx = blockIdx.x;
    const int i = idx & (SS - 1);
    const int bh = idx >> 9;
    const int b = bh >> 3;
    float* srow = sc + ((size_t)bh * SS + i) * SS;
    const float* trow = t0 + ((size_t)(b * SS) + i) * SS;
    const float c = consts[b * 2], d = consts[b * 2 + 1];
    const int t = threadIdx.x;

    float4 s4 = *(float4*)&srow[t * 4];
    float4 t4 = *(const float4*)&trow[t * 4];
    float f[4];
    f[0] = fminf(fmaxf(s4.x + 0.1f * fmaf(c, t4.x, d), -15.f), 15.f);
    f[1] = fminf(fmaxf(s4.y + 0.1f * fmaf(c, t4.y, d), -15.f), 15.f);
    f[2] = fminf(fmaxf(s4.z + 0.1f * fmaf(c, t4.z, d), -15.f), 15.f);
    f[3] = fminf(fmaxf(s4.w + 0.1f * fmaf(c, t4.w, d), -15.f), 15.f);
    float lmax = fmaxf(fmaxf(f[0], f[1]), fmaxf(f[2], f[3]));
    red[t] = lmax; __syncthreads();
    for (int s2 = 64; s2 > 0; s2 >>= 1) {
        if (t < s2) red[t] = fmaxf(red[t], red[t + s2]);
        __syncthreads();
    }
    float rmax = red[0]; __syncthreads();
    float lsum = 0.f;
    #pragma unroll
    for (int e = 0; e < 4; e++) { f[e] = expf(f[e] - rmax); lsum += f[e]; }
    red[t] = lsum; __syncthreads();
    for (int s2 = 64; s2 > 0; s2 >>= 1) {
        if (t < s2) red[t] += red[t + s2];
        __syncthreads();
    }
    float inv = 1.f / red[0];
    *(float4*)&srow[t * 4] = make_float4(f[0] * inv, f[1] * inv, f[2] * inv, f[3] * inv);
}

// ---------------- host ----------------
extern "C" void kernel_launch(void* const* d_in, const int* in_sizes, int n_in,
                              void* d_out, int out_size) {
    const float* x  = (const float*)d_in[0];
    const float* wq = (const float*)d_in[1];
    const float* bq = (const float*)d_in[2];
    const float* wk = (const float*)d_in[3];
    const float* bk = (const float*)d_in[4];
    const float* wv = (const float*)d_in[5];
    const float* bv = (const float*)d_in[6];
    const float* wo = (const float*)d_in[7];
    const float* bo = (const float*)d_in[8];
    const float* w1 = (const float*)d_in[9];
    const float* b1 = (const float*)d_in[10];
    const float* w2 = (const float*)d_in[11];
    const float* b2 = (const float*)d_in[12];
    float* out = (float*)d_out;

    float *q, *k, *v, *scores, *meanb, *t0, *rowstats, *consts, *attnout, *lut;
    cudaGetSymbolAddress((void**)&q, g_q);
    cudaGetSymbolAddress((void**)&k, g_k);
    cudaGetSymbolAddress((void**)&v, g_v);
    cudaGetSymbolAddress((void**)&scores, g_scores);
    cudaGetSymbolAddress((void**)&meanb, g_mean);
    cudaGetSymbolAddress((void**)&t0, g_t0);
    cudaGetSymbolAddress((void**)&rowstats, g_rowstats);
    cudaGetSymbolAddress((void**)&consts, g_consts);
    cudaGetSymbolAddress((void**)&attnout, g_attnout);
    cudaGetSymbolAddress((void**)&lut, g_lut);

    __nv_bfloat16 *xhi, *xlo, *wqhi, *wqlo, *wkhi, *wklo, *wvhi, *wvlo, *wohi, *wolo, *aohi, *aolo;
    cudaGetSymbolAddress((void**)&xhi, g_xhi);   cudaGetSymbolAddress((void**)&xlo, g_xlo);
    cudaGetSymbolAddress((void**)&wqhi, g_wqhi); cudaGetSymbolAddress((void**)&wqlo, g_wqlo);
    cudaGetSymbolAddress((void**)&wkhi, g_wkhi); cudaGetSymbolAddress((void**)&wklo, g_wklo);
    cudaGetSymbolAddress((void**)&wvhi, g_wvhi); cudaGetSymbolAddress((void**)&wvlo, g_wvlo);
    cudaGetSymbolAddress((void**)&wohi, g_wohi); cudaGetSymbolAddress((void**)&wolo, g_wolo);
    cudaGetSymbolAddress((void**)&aohi, g_aohi); cudaGetSymbolAddress((void**)&aolo, g_aolo);

    lut_kernel<<<17, 256>>>(w1, b1, w2, b2, lut);

    cvt_kernel<<<512, 256>>>(x, xhi, xlo);
    cvt_kernel<<<128, 256>>>(wq, wqhi, wqlo);
    cvt_kernel<<<128, 256>>>(wk, wkhi, wklo);
    cvt_kernel<<<128, 256>>>(wv, wvhi, wvlo);
    cvt_kernel<<<128, 256>>>(wo, wohi, wolo);

    hqkv_gemm<<<dim3(8, 16, 3), 256>>>(xhi, xlo, wqhi, wqlo, bq,
                                       wkhi, wklo, bk, wvhi, wvlo, bv, q, k, v);

    scores_gemm<<<dim3(8, 4, 32), 256>>>(q, k, scores);

    mean_kernel<<<1024, 256>>>((const float4*)scores, (float4*)meanb);
    rowtrans_kernel<<<BB * SS, 256>>>(meanb, lut, t0, rowstats);
    bconst_kernel<<<BB, 256>>>(rowstats, consts);
    probs_kernel<<<BB * HH * SS, 128>>>(scores, t0, consts);

    pv_gemm<<<dim3(1, 4, 32), 256>>>(scores, v, attnout);

    cvt_kernel<<<512, 256>>>(attnout, aohi, aolo);
    hout_gemm<<<dim3(8, 16), 256>>>(aohi, aolo, wohi, wolo, bo, out);
}